// round 11
// baseline (speedup 1.0000x reference)
#include <cuda_runtime.h>
#include <cuda_fp16.h>
#include <cstdint>

// ---------------------------------------------------------------------------
// Problem constants
// ---------------------------------------------------------------------------
#define BATCH 2
#define SEQ   4096
#define DIM   256
#define NROWS (BATCH * SEQ)        // 8192 rows per view
#define NVIEW 3
#define NVB   (NVIEW * BATCH)      // 6 attention slices
#define IN3   (NVIEW * DIM)        // 768
#define NB    8
#define KCOMB (IN3 + IN3 * NB)     // 6912
#define QKVN  (3 * DIM)            // 768 packed q|k|v columns
#define ROWS3 (NVIEW * NROWS)      // 24576

// ---------------------------------------------------------------------------
// Device scratch (static only -- no cudaMalloc allowed)
// ---------------------------------------------------------------------------
__device__ __half g_tok [(size_t)ROWS3 * DIM];        // fp16 tokens (concat views)
__device__ __half g_wqkv[(size_t)QKVN * DIM];         // packed [wq;wk;wv] fp16
__device__ float  g_bqkv[QKVN];
__device__ __half g_qkv [(size_t)ROWS3 * QKVN];       // 37.7 MB [row][q|k|v]
__device__ __half g_vt  [(size_t)NVB * DIM * SEQ];    // 12.5 MB V^T per slice
__device__ __half g_s   [(size_t)NVB * SEQ * SEQ];    // 202 MB fp16 scores->probs
__device__ float  g_att [(size_t)ROWS3 * DIM];
__device__ float  g_x   [(size_t)NROWS * IN3];
__device__ __half g_a   [(size_t)NROWS * KCOMB];      // 113 MB
__device__ __half g_w   [(size_t)DIM * KCOMB];
__device__ float  g_part[2][(size_t)NROWS * DIM];     // split-K partials (50 MB)

// ---------------------------------------------------------------------------
// Async / mma / ldmatrix helpers
// ---------------------------------------------------------------------------
__device__ __forceinline__ void cp16(void* smem_dst, const void* gsrc) {
    uint32_t d = (uint32_t)__cvta_generic_to_shared(smem_dst);
    asm volatile("cp.async.cg.shared.global [%0], [%1], 16;" :: "r"(d), "l"(gsrc));
}
__device__ __forceinline__ void cp_commit() { asm volatile("cp.async.commit_group;"); }
template <int N>
__device__ __forceinline__ void cp_wait() { asm volatile("cp.async.wait_group %0;" :: "n"(N)); }

__device__ __forceinline__ void mma_f16(float c[4],
                                        uint32_t a0, uint32_t a1, uint32_t a2, uint32_t a3,
                                        uint32_t b0, uint32_t b1) {
    asm("mma.sync.aligned.m16n8k16.row.col.f32.f16.f16.f32 "
        "{%0,%1,%2,%3}, {%4,%5,%6,%7}, {%8,%9}, {%0,%1,%2,%3};"
        : "+f"(c[0]), "+f"(c[1]), "+f"(c[2]), "+f"(c[3])
        : "r"(a0), "r"(a1), "r"(a2), "r"(a3), "r"(b0), "r"(b1));
}

__device__ __forceinline__ void ldsm_x4(uint32_t& r0, uint32_t& r1,
                                        uint32_t& r2, uint32_t& r3, uint32_t addr) {
    asm volatile("ldmatrix.sync.aligned.m8n8.x4.shared.b16 {%0,%1,%2,%3}, [%4];"
                 : "=r"(r0), "=r"(r1), "=r"(r2), "=r"(r3) : "r"(addr));
}

// ---------------------------------------------------------------------------
// FP16 tensor-core GEMM (NT): C = A @ B^T (+bias), fp32 accumulate.
// 128x128x32 tiles, 4-stage cp.async pipeline, pad-40 rows, 2 CTAs/SM.
// Fragment loads via NON-TRANS ldmatrix.x4 for both A and B: with NT storage
// ([m][k] and [n][k] row-major) both fragments have layout M[g][2t..2t+1]
// per octet, which is exactly what non-trans ldmatrix delivers.
// Pad-40 row stride (80B) -> every 8-lane ldmatrix phase is bank-conflict-free.
// ---------------------------------------------------------------------------
#define STAGES 4
#define AROW   40
#define STG_H  (128 * AROW)

template <bool OUTH>
__global__ __launch_bounds__(256, 2)
void hgemm(const __half* __restrict__ A, int lda,
           const __half* __restrict__ B, int ldb,
           void* __restrict__ Cv, int ldc, int K,
           long sA, long sB, long sC,
           const float* __restrict__ bias)
{
    A += (long)blockIdx.z * sA;
    B += (long)blockIdx.z * sB;

    extern __shared__ __half sm[];
    __half* Asm = sm;
    __half* Bsm = sm + STAGES * STG_H;

    const int bm = blockIdx.y * 128;
    const int bn = blockIdx.x * 128;

    const int tid  = threadIdx.x;
    const int warp = tid >> 5, lane = tid & 31;
    const int wm = warp & 3;
    const int wn = warp >> 2;
    const int g = lane >> 2, t = lane & 3;

    const int r0 = tid >> 2;
    const int q8 = (tid & 3) * 8;

    // ldmatrix lane addressing (offsets in halfs, ks=0)
    // A tile mt: matrices {(m,k0),(m+8,k0),(m,k0+8),(m+8,k0+8)} -> a0..a3
    // B pair p (n-octets 2p,2p+1): matrices {(n,k0),(n,k0+8),(n+8,k0),(n+8,k0+8)}
    //   -> r0=b[2p][0], r1=b[2p][1], r2=b[2p+1][0], r3=b[2p+1][1]
    const int mat = lane >> 3, mrow = lane & 7;
    uint32_t aoff[2], boff[4];
    #pragma unroll
    for (int mt = 0; mt < 2; ++mt)
        aoff[mt] = (uint32_t)((wm * 32 + mt * 16 + (mat & 1) * 8 + mrow) * AROW
                              + (mat >> 1) * 8);
    #pragma unroll
    for (int p = 0; p < 4; ++p)
        boff[p] = (uint32_t)((wn * 64 + p * 16 + (mat >> 1) * 8 + mrow) * AROW
                             + (mat & 1) * 8);

    const uint32_t AsmBase = (uint32_t)__cvta_generic_to_shared(Asm);
    const uint32_t BsmBase = (uint32_t)__cvta_generic_to_shared(Bsm);

    float acc[2][8][4] = {};
    const int niter = K >> 5;

    auto fetch = [&](int stage, int k0) {
        __half* as = Asm + stage * STG_H;
        __half* bs = Bsm + stage * STG_H;
        #pragma unroll
        for (int j = 0; j < 2; ++j) {
            const int r = r0 + 64 * j;
            cp16(&as[r * AROW + q8], A + (long)(bm + r) * lda + k0 + q8);
            cp16(&bs[r * AROW + q8], B + (long)(bn + r) * ldb + k0 + q8);
        }
    };

    #pragma unroll
    for (int s = 0; s < STAGES - 1; ++s) {
        if (s < niter) fetch(s, s * 32);
        cp_commit();
    }

    for (int i = 0; i < niter; ++i) {
        cp_wait<STAGES - 2>();
        __syncthreads();

        const int pf = i + STAGES - 1;
        if (pf < niter) fetch(pf % STAGES, pf * 32);
        cp_commit();

        const uint32_t aBase = AsmBase + (uint32_t)((i % STAGES) * STG_H) * 2u;
        const uint32_t bBase = BsmBase + (uint32_t)((i % STAGES) * STG_H) * 2u;

        #pragma unroll
        for (int ks = 0; ks < 2; ++ks) {
            const uint32_t kadd = (uint32_t)(ks * 16) * 2u;
            uint32_t a[2][4];
            #pragma unroll
            for (int mt = 0; mt < 2; ++mt)
                ldsm_x4(a[mt][0], a[mt][1], a[mt][2], a[mt][3],
                        aBase + aoff[mt] * 2u + kadd);
            uint32_t b[8][2];
            #pragma unroll
            for (int p = 0; p < 4; ++p)
                ldsm_x4(b[2 * p][0], b[2 * p][1], b[2 * p + 1][0], b[2 * p + 1][1],
                        bBase + boff[p] * 2u + kadd);
            #pragma unroll
            for (int mt = 0; mt < 2; ++mt)
                #pragma unroll
                for (int nt = 0; nt < 8; ++nt)
                    mma_f16(acc[mt][nt], a[mt][0], a[mt][1], a[mt][2], a[mt][3],
                            b[nt][0], b[nt][1]);
        }
        __syncthreads();
    }

    #pragma unroll
    for (int mt = 0; mt < 2; ++mt) {
        const int m = bm + wm * 32 + mt * 16 + g;
        #pragma unroll
        for (int nt = 0; nt < 8; ++nt) {
            const int n = bn + wn * 64 + nt * 8 + 2 * t;
            float bx = 0.f, by = 0.f;
            if (bias) { bx = bias[n]; by = bias[n + 1]; }
            const float v0 = acc[mt][nt][0] + bx, v1 = acc[mt][nt][1] + by;
            const float v2 = acc[mt][nt][2] + bx, v3 = acc[mt][nt][3] + by;
            if (OUTH) {
                __half* C = (__half*)Cv + blockIdx.z * sC;
                *(__half2*)(C + (long)m * ldc + n)       = __floats2half2_rn(v0, v1);
                *(__half2*)(C + (long)(m + 8) * ldc + n) = __floats2half2_rn(v2, v3);
            } else {
                float* C = (float*)Cv + blockIdx.z * sC;
                *(float2*)(C + (long)m * ldc + n)       = make_float2(v0, v1);
                *(float2*)(C + (long)(m + 8) * ldc + n) = make_float2(v2, v3);
            }
        }
    }
}

// ---------------------------------------------------------------------------
// Transpose V slices: qkv[slice][key][512+d] -> vt[slice][d][key]  (fp16)
// ---------------------------------------------------------------------------
__global__ __launch_bounds__(256)
void transpose_v(const __half* __restrict__ qkv, __half* __restrict__ vt)
{
    __shared__ __half tile[32][40];
    const int s  = blockIdx.z;
    const __half* src = qkv + (size_t)s * SEQ * QKVN + 2 * DIM;
    __half* dst = vt + (size_t)s * DIM * SEQ;
    const int k0 = blockIdx.x * 32, d0 = blockIdx.y * 32;
    const int tx = threadIdx.x & 31, ty = threadIdx.x >> 5;
    #pragma unroll
    for (int j = 0; j < 4; ++j)
        tile[ty + 8 * j][tx] = src[(size_t)(k0 + ty + 8 * j) * QKVN + d0 + tx];
    __syncthreads();
    #pragma unroll
    for (int j = 0; j < 4; ++j)
        dst[(size_t)(d0 + ty + 8 * j) * SEQ + k0 + tx] = tile[tx][ty + 8 * j];
}

// ---------------------------------------------------------------------------
// Row softmax over fp16 scores, in place: p = softmax(s / 16).
// ---------------------------------------------------------------------------
__global__ __launch_bounds__(256)
void softmax_h(__half* __restrict__ S, float scale)
{
    __half* row = S + (size_t)blockIdx.x * SEQ;
    const int tid = threadIdx.x;
    __shared__ float red[8];

    float v[16];
    #pragma unroll
    for (int j = 0; j < 2; ++j) {
        const __half2* p = (const __half2*)(row + (j * 256 + tid) * 8);
        #pragma unroll
        for (int q = 0; q < 4; ++q) {
            const float2 f = __half22float2(p[q]);
            v[j * 8 + 2 * q]     = f.x;
            v[j * 8 + 2 * q + 1] = f.y;
        }
    }

    float m = -1e30f;
    #pragma unroll
    for (int i = 0; i < 16; ++i) m = fmaxf(m, v[i]);
    #pragma unroll
    for (int o = 16; o; o >>= 1) m = fmaxf(m, __shfl_xor_sync(0xffffffffu, m, o));
    if ((tid & 31) == 0) red[tid >> 5] = m;
    __syncthreads();
    m = red[0];
    #pragma unroll
    for (int i = 1; i < 8; ++i) m = fmaxf(m, red[i]);
    __syncthreads();

    float sum = 0.f;
    #pragma unroll
    for (int i = 0; i < 16; ++i) {
        v[i] = __expf(scale * (v[i] - m));
        sum += v[i];
    }
    #pragma unroll
    for (int o = 16; o; o >>= 1) sum += __shfl_xor_sync(0xffffffffu, sum, o);
    if ((tid & 31) == 0) red[tid >> 5] = sum;
    __syncthreads();
    sum = 0.f;
    #pragma unroll
    for (int i = 0; i < 8; ++i) sum += red[i];
    const float inv = 1.f / sum;

    #pragma unroll
    for (int j = 0; j < 2; ++j) {
        __half2* p = (__half2*)(row + (j * 256 + tid) * 8);
        #pragma unroll
        for (int q = 0; q < 4; ++q)
            p[q] = __floats2half2_rn(v[j * 8 + 2 * q] * inv, v[j * 8 + 2 * q + 1] * inv);
    }
}

// ---------------------------------------------------------------------------
// Round-copy fp32 tokens -> fp16 scratch
// ---------------------------------------------------------------------------
__global__ __launch_bounds__(256)
void round_copy_h(const float* __restrict__ src, __half* __restrict__ dst, int n)
{
    const int i = blockIdx.x * 1024 + threadIdx.x * 4;
    if (i >= n) return;
    float4 v = *(const float4*)(src + i);
    *(__half2*)(dst + i)     = __floats2half2_rn(v.x, v.y);
    *(__half2*)(dst + i + 2) = __floats2half2_rn(v.z, v.w);
}

// ---------------------------------------------------------------------------
// Pack [wq;wk;wv] -> g_wqkv (fp16) and biases -> g_bqkv (fp32)
// ---------------------------------------------------------------------------
__global__ __launch_bounds__(256)
void build_wqkv(const float* __restrict__ wq, const float* __restrict__ wk,
                const float* __restrict__ wv, const float* __restrict__ bq,
                const float* __restrict__ bk, const float* __restrict__ bv,
                __half* __restrict__ W, float* __restrict__ Bb)
{
    const int idx = blockIdx.x * 256 + threadIdx.x;
    if (idx >= QKVN * DIM) return;
    const int r = idx / DIM, c = idx % DIM;
    const float* w = (r < DIM) ? wq : (r < 2 * DIM) ? wk : wv;
    W[idx] = __float2half_rn(w[(r & (DIM - 1)) * DIM + c]);
    if (idx < QKVN) {
        const float* b = (idx < DIM) ? bq : (idx < 2 * DIM) ? bk : bv;
        Bb[idx] = b[idx & (DIM - 1)];
    }
}

// ---------------------------------------------------------------------------
// y = LayerNorm(att + tokens) * g + b -> concatenated x buffer (fp32)
// ---------------------------------------------------------------------------
__global__ __launch_bounds__(256)
void resid_ln_kernel(const float* __restrict__ att, const float* __restrict__ tok,
                     const float* __restrict__ g, const float* __restrict__ b,
                     float* __restrict__ xout, int view)
{
    const long row = blockIdx.x;
    const int d = threadIdx.x;
    __shared__ float red[8];

    const float v = att[row * DIM + d] + tok[row * DIM + d];

    float s = v;
    #pragma unroll
    for (int o = 16; o; o >>= 1) s += __shfl_xor_sync(0xffffffffu, s, o);
    if ((d & 31) == 0) red[d >> 5] = s;
    __syncthreads();
    float mean = 0.f;
    #pragma unroll
    for (int i = 0; i < 8; ++i) mean += red[i];
    mean *= (1.f / DIM);
    __syncthreads();

    const float c = v - mean;
    float s2 = c * c;
    #pragma unroll
    for (int o = 16; o; o >>= 1) s2 += __shfl_xor_sync(0xffffffffu, s2, o);
    if ((d & 31) == 0) red[d >> 5] = s2;
    __syncthreads();
    float var = 0.f;
    #pragma unroll
    for (int i = 0; i < 8; ++i) var += red[i];
    var *= (1.f / DIM);

    const float y = c * rsqrtf(var + 1e-5f) * g[d] + b[d];
    xout[row * IN3 + (long)view * DIM + d] = y;
}

// ---------------------------------------------------------------------------
// Combined weight: [base_w | spline_w * scaler] -> fp16
// ---------------------------------------------------------------------------
__global__ __launch_bounds__(256)
void build_w_kernel(const float* __restrict__ bw, const float* __restrict__ sw,
                    const float* __restrict__ sc, __half* __restrict__ W)
{
    const long idx = (long)blockIdx.x * blockDim.x + threadIdx.x;
    if (idx >= (long)DIM * IN3) return;
    const int o = (int)(idx / IN3);
    const int i = (int)(idx % IN3);
    W[(long)o * KCOMB + i] = __float2half_rn(bw[(long)o * IN3 + i]);
    const float s = sc[(long)o * IN3 + i];
    const float* swp = sw + ((long)o * IN3 + i) * NB;
    __half* wp = W + (long)o * KCOMB + IN3 + (long)i * NB;
    #pragma unroll
    for (int f = 0; f < NB; ++f) wp[f] = __float2half_rn(swp[f] * s);
}

// ---------------------------------------------------------------------------
// Combined A: [silu(x) | cubic b-spline bases] -> fp16
// ---------------------------------------------------------------------------
__global__ __launch_bounds__(256)
void build_a_kernel(const float* __restrict__ x, __half* __restrict__ A)
{
    const long idx = (long)blockIdx.x * blockDim.x + threadIdx.x;
    if (idx >= (long)NROWS * IN3) return;
    const long n = idx / IN3;
    const int i = (int)(idx % IN3);
    const float v = x[idx];

    const float sig = 1.f / (1.f + __expf(-v));
    A[n * KCOMB + i] = __float2half_rn(v * sig);

    const float h = 0.4f;
    float b[11];
    #pragma unroll
    for (int j = 0; j < 11; ++j) {
        const float gj  = -1.f + (j - 3) * h;
        const float gj1 = -1.f + (j - 2) * h;
        b[j] = (v >= gj && v < gj1) ? 1.f : 0.f;
    }
    #pragma unroll
    for (int k = 1; k <= 3; ++k) {
        #pragma unroll
        for (int j = 0; j <= 10 - k; ++j) {
            const float gj   = -1.f + (j - 3) * h;
            const float gjk  = -1.f + (j - 3 + k) * h;
            const float gj1  = -1.f + (j - 2) * h;
            const float gjk1 = -1.f + (j - 2 + k) * h;
            b[j] = (v - gj) / (gjk - gj) * b[j] + (gjk1 - v) / (gjk1 - gj1) * b[j + 1];
        }
    }
    __half* ap = A + n * KCOMB + IN3 + (long)i * NB;
    #pragma unroll
    for (int f = 0; f < NB; ++f) ap[f] = __float2half_rn(b[f]);
}

// ---------------------------------------------------------------------------
// out = part0 + part1 (split-K reduction, fixed order -> deterministic)
// ---------------------------------------------------------------------------
__global__ __launch_bounds__(256)
void add2_kernel(const float* __restrict__ p0, const float* __restrict__ p1,
                 float* __restrict__ out, int n)
{
    const int i = blockIdx.x * 1024 + threadIdx.x * 4;
    if (i >= n) return;
    float4 a = *(const float4*)(p0 + i);
    float4 b = *(const float4*)(p1 + i);
    a.x += b.x; a.y += b.y; a.z += b.z; a.w += b.w;
    *(float4*)(out + i) = a;
}

// ---------------------------------------------------------------------------
// Host launcher
// ---------------------------------------------------------------------------
extern "C" void kernel_launch(void* const* d_in, const int* in_sizes, int n_in,
                              void* d_out, int out_size)
{
    (void)in_sizes; (void)n_in; (void)out_size;

    const float* tok[NVIEW] = {(const float*)d_in[0], (const float*)d_in[1], (const float*)d_in[2]};
    const float* wq = (const float*)d_in[3];
    const float* bq = (const float*)d_in[4];
    const float* wk = (const float*)d_in[5];
    const float* bk = (const float*)d_in[6];
    const float* wv = (const float*)d_in[7];
    const float* bv = (const float*)d_in[8];
    // d_in[9] = view_emb: per-query constant bias -> softmax-invariant -> unused
    const float* lng[NVIEW] = {(const float*)d_in[10], (const float*)d_in[12], (const float*)d_in[14]};
    const float* lnb[NVIEW] = {(const float*)d_in[11], (const float*)d_in[13], (const float*)d_in[15]};
    const float* bw = (const float*)d_in[16];
    const float* sw = (const float*)d_in[17];
    const float* sc = (const float*)d_in[18];

    __half *ptok, *pwqkv, *pqkv, *pvt, *ps, *pa, *pw;
    float *pbqkv, *att, *x, *ppart;
    cudaGetSymbolAddress((void**)&ptok,  g_tok);
    cudaGetSymbolAddress((void**)&pwqkv, g_wqkv);
    cudaGetSymbolAddress((void**)&pbqkv, g_bqkv);
    cudaGetSymbolAddress((void**)&pqkv,  g_qkv);
    cudaGetSymbolAddress((void**)&pvt,   g_vt);
    cudaGetSymbolAddress((void**)&ps,    g_s);
    cudaGetSymbolAddress((void**)&att,   g_att);
    cudaGetSymbolAddress((void**)&x,     g_x);
    cudaGetSymbolAddress((void**)&pa,    g_a);
    cudaGetSymbolAddress((void**)&pw,    g_w);
    cudaGetSymbolAddress((void**)&ppart, g_part);

    const int SMEM = STAGES * STG_H * 2 * (int)sizeof(__half);   // 81920 B
    cudaFuncSetAttribute(hgemm<true>,  cudaFuncAttributeMaxDynamicSharedMemorySize, SMEM);
    cudaFuncSetAttribute(hgemm<false>, cudaFuncAttributeMaxDynamicSharedMemorySize, SMEM);

    const long qkvSlice = (long)SEQ * QKVN;
    const long sStride  = (long)SEQ * SEQ;

    // 0) pack tokens (fp16) and qkv weights
    const int ntok = NROWS * DIM;
    for (int vi = 0; vi < NVIEW; ++vi)
        round_copy_h<<<(ntok + 1023) / 1024, 256>>>(tok[vi], ptok + (long)vi * ntok, ntok);
    build_wqkv<<<(QKVN * DIM + 255) / 256, 256>>>(wq, wk, wv, bq, bk, bv, pwqkv, pbqkv);

    // 1) fused QKV: [24576,768] = tok @ Wqkv^T + bqkv -> fp16
    {
        dim3 grid(QKVN / 128, ROWS3 / 128, 1);
        hgemm<true><<<grid, 256, SMEM>>>(ptok, DIM, pwqkv, DIM, pqkv, QKVN,
                                         DIM, 0, 0, 0, pbqkv);
    }

    // 1b) transpose V slices -> g_vt
    {
        dim3 grid(SEQ / 32, DIM / 32, NVB);
        transpose_v<<<grid, 256>>>(pqkv, pvt);
    }

    // 2) scores = Q @ K^T (fp16 out), all 6 slices
    {
        dim3 grid(SEQ / 128, SEQ / 128, NVB);
        hgemm<true><<<grid, 256, SMEM>>>(pqkv, QKVN, pqkv + DIM, QKVN, ps, SEQ,
                                         DIM, qkvSlice, qkvSlice, sStride, nullptr);
    }

    // 3) softmax(scores / 16) in place -> fp16 probs
    softmax_h<<<NVB * SEQ, 256>>>(ps, 0.0625f);

    // 4) att = P @ Vt^T (NT, fp32 out)
    {
        dim3 grid(DIM / 128, SEQ / 128, NVB);
        hgemm<false><<<grid, 256, SMEM>>>(ps, SEQ, pvt, SEQ, att, DIM,
                                          SEQ, sStride, (long)DIM * SEQ, (long)SEQ * DIM, nullptr);
    }

    // 5) LayerNorm(att + tokens) -> concat x (fp32)
    for (int vi = 0; vi < NVIEW; ++vi)
        resid_ln_kernel<<<NROWS, 256>>>(att + (long)vi * NROWS * DIM, tok[vi],
                                        lng[vi], lnb[vi], x, vi);

    // 6) combined weight / combined A (fp16)
    build_w_kernel<<<(DIM * IN3 + 255) / 256, 256>>>(bw, sw, sc, pw);
    build_a_kernel<<<(int)(((long)NROWS * IN3 + 255) / 256), 256>>>(x, pa);

    // 7) out = A @ W^T via split-K=2 (256 CTAs), then deterministic add
    {
        dim3 grid(DIM / 128, NROWS / 128, 2);
        hgemm<false><<<grid, 256, SMEM>>>(pa, KCOMB, pw, KCOMB, ppart, DIM,
                                          KCOMB / 2, KCOMB / 2, KCOMB / 2,
                                          (long)NROWS * DIM, nullptr);
        add2_kernel<<<(NROWS * DIM + 1023) / 1024, 256>>>(
            ppart, ppart + (long)NROWS * DIM, (float*)d_out, NROWS * DIM);
    }
}

// round 14
// speedup vs baseline: 1.8483x; 1.8483x over previous
#include <cuda_runtime.h>
#include <cuda_fp16.h>
#include <cstdint>

// ---------------------------------------------------------------------------
// Problem constants
// ---------------------------------------------------------------------------
#define BATCH 2
#define SEQ   4096
#define DIM   256
#define NROWS (BATCH * SEQ)        // 8192 rows per view
#define NVIEW 3
#define NVB   (NVIEW * BATCH)      // 6 attention slices
#define IN3   (NVIEW * DIM)        // 768
#define NB    8
#define KCOMB (IN3 + IN3 * NB)     // 6912
#define QKVN  (3 * DIM)            // 768 packed q|k|v columns
#define ROWS3 (NVIEW * NROWS)      // 24576

// ---------------------------------------------------------------------------
// Device scratch (static only -- no cudaMalloc allowed)
// ---------------------------------------------------------------------------
__device__ __half g_tok [(size_t)ROWS3 * DIM];        // fp16 tokens (concat views)
__device__ __half g_wqkv[(size_t)QKVN * DIM];         // packed [wq;wk;wv] fp16
__device__ float  g_bqkv[QKVN];
__device__ __half g_qkv [(size_t)ROWS3 * QKVN];       // 37.7 MB [row][q|k|v]
__device__ __half g_vt  [(size_t)NVB * DIM * SEQ];    // 12.5 MB V^T per slice
__device__ __half g_s   [(size_t)NVB * SEQ * SEQ];    // 202 MB fp16 scores->probs
__device__ float  g_att [(size_t)ROWS3 * DIM];
__device__ float  g_x   [(size_t)NROWS * IN3];
__device__ __half g_a   [(size_t)NROWS * KCOMB];      // 113 MB
__device__ __half g_w   [(size_t)DIM * KCOMB];
__device__ float  g_part[2][(size_t)NROWS * DIM];     // split-K partials (50 MB)

// ---------------------------------------------------------------------------
// Async / mma helpers
// ---------------------------------------------------------------------------
__device__ __forceinline__ void cp16(void* smem_dst, const void* gsrc) {
    uint32_t d = (uint32_t)__cvta_generic_to_shared(smem_dst);
    asm volatile("cp.async.cg.shared.global [%0], [%1], 16;" :: "r"(d), "l"(gsrc));
}
__device__ __forceinline__ void cp_commit() { asm volatile("cp.async.commit_group;"); }
template <int N>
__device__ __forceinline__ void cp_wait() { asm volatile("cp.async.wait_group %0;" :: "n"(N)); }

__device__ __forceinline__ void mma_f16(float c[4],
                                        uint32_t a0, uint32_t a1, uint32_t a2, uint32_t a3,
                                        uint32_t b0, uint32_t b1) {
    asm("mma.sync.aligned.m16n8k16.row.col.f32.f16.f16.f32 "
        "{%0,%1,%2,%3}, {%4,%5,%6,%7}, {%8,%9}, {%0,%1,%2,%3};"
        : "+f"(c[0]), "+f"(c[1]), "+f"(c[2]), "+f"(c[3])
        : "r"(a0), "r"(a1), "r"(a2), "r"(a3), "r"(b0), "r"(b1));
}

// ---------------------------------------------------------------------------
// FP16 tensor-core GEMM (NT): C = A @ B^T (+bias), fp32 accumulate.
// 128x128x64 tiles, 3-stage cp.async pipeline, pad-72 rows (144B stride:
// fragment LDS banks = 4g+t+const, conflict-free), 2 CTAs/SM, ONE barrier
// per mainloop iteration (write stage (i+2)%3 was last read at i-1, whose
// reads complete before the top-of-iter barrier).
// Scalar-LDS fragment loads (proven fastest variant; do not ldmatrix).
// All call-site K are multiples of 64; M,N multiples of 128.
// ---------------------------------------------------------------------------
#define STAGES 3
#define AROW   72                  // halfs per smem row (64 data + 8 pad)
#define STG_H  (128 * AROW)

template <bool OUTH>
__global__ __launch_bounds__(256, 2)
void hgemm(const __half* __restrict__ A, int lda,
           const __half* __restrict__ B, int ldb,
           void* __restrict__ Cv, int ldc, int K,
           long sA, long sB, long sC,
           const float* __restrict__ bias)
{
    A += (long)blockIdx.z * sA;
    B += (long)blockIdx.z * sB;

    extern __shared__ __half sm[];
    __half* Asm = sm;
    __half* Bsm = sm + STAGES * STG_H;

    const int bm = blockIdx.y * 128;
    const int bn = blockIdx.x * 128;

    const int tid  = threadIdx.x;
    const int warp = tid >> 5, lane = tid & 31;
    const int wm = warp & 3;
    const int wn = warp >> 2;
    const int g = lane >> 2, t = lane & 3;

    const int r0 = tid >> 3;           // 0..31 (+32j)
    const int q8 = (tid & 7) * 8;      // half col offset within 64-wide k row

    float acc[2][8][4] = {};
    const int niter = K >> 6;

    auto fetch = [&](int stage, int k0) {
        __half* as = Asm + stage * STG_H;
        __half* bs = Bsm + stage * STG_H;
        #pragma unroll
        for (int j = 0; j < 4; ++j) {
            const int r = r0 + 32 * j;
            cp16(&as[r * AROW + q8], A + (long)(bm + r) * lda + k0 + q8);
            cp16(&bs[r * AROW + q8], B + (long)(bn + r) * ldb + k0 + q8);
        }
    };

    #pragma unroll
    for (int s = 0; s < STAGES - 1; ++s) {
        if (s < niter) fetch(s, s * 64);
        cp_commit();
    }

    for (int i = 0; i < niter; ++i) {
        cp_wait<STAGES - 2>();
        __syncthreads();

        const int pf = i + STAGES - 1;
        if (pf < niter) fetch(pf % STAGES, pf * 64);
        cp_commit();

        const __half* as = Asm + (i % STAGES) * STG_H;
        const __half* bs = Bsm + (i % STAGES) * STG_H;

        #pragma unroll
        for (int ks = 0; ks < 4; ++ks) {
            const int kk = ks * 16 + 2 * t;
            uint32_t a[2][4];
            #pragma unroll
            for (int mt = 0; mt < 2; ++mt) {
                const int m = wm * 32 + mt * 16 + g;
                const uint32_t* p0 = (const uint32_t*)&as[m * AROW + kk];
                const uint32_t* p1 = (const uint32_t*)&as[(m + 8) * AROW + kk];
                a[mt][0] = p0[0];
                a[mt][1] = p1[0];
                a[mt][2] = p0[4];
                a[mt][3] = p1[4];
            }
            uint32_t b[8][2];
            #pragma unroll
            for (int nt = 0; nt < 8; ++nt) {
                const int n = wn * 64 + nt * 8 + g;
                const uint32_t* pb = (const uint32_t*)&bs[n * AROW + kk];
                b[nt][0] = pb[0];
                b[nt][1] = pb[4];
            }
            #pragma unroll
            for (int mt = 0; mt < 2; ++mt)
                #pragma unroll
                for (int nt = 0; nt < 8; ++nt)
                    mma_f16(acc[mt][nt], a[mt][0], a[mt][1], a[mt][2], a[mt][3],
                            b[nt][0], b[nt][1]);
        }
        // no trailing barrier: next iteration's top barrier provides the
        // cross-warp ordering before stage reuse (STAGES >= 3).
    }

    #pragma unroll
    for (int mt = 0; mt < 2; ++mt) {
        const int m = bm + wm * 32 + mt * 16 + g;
        #pragma unroll
        for (int nt = 0; nt < 8; ++nt) {
            const int n = bn + wn * 64 + nt * 8 + 2 * t;
            float bx = 0.f, by = 0.f;
            if (bias) { bx = bias[n]; by = bias[n + 1]; }
            const float v0 = acc[mt][nt][0] + bx, v1 = acc[mt][nt][1] + by;
            const float v2 = acc[mt][nt][2] + bx, v3 = acc[mt][nt][3] + by;
            if (OUTH) {
                __half* C = (__half*)Cv + blockIdx.z * sC;
                *(__half2*)(C + (long)m * ldc + n)       = __floats2half2_rn(v0, v1);
                *(__half2*)(C + (long)(m + 8) * ldc + n) = __floats2half2_rn(v2, v3);
            } else {
                float* C = (float*)Cv + blockIdx.z * sC;
                *(float2*)(C + (long)m * ldc + n)       = make_float2(v0, v1);
                *(float2*)(C + (long)(m + 8) * ldc + n) = make_float2(v2, v3);
            }
        }
    }
}

// ---------------------------------------------------------------------------
// Transpose V slices: qkv[slice][key][512+d] -> vt[slice][d][key]  (fp16)
// ---------------------------------------------------------------------------
__global__ __launch_bounds__(256)
void transpose_v(const __half* __restrict__ qkv, __half* __restrict__ vt)
{
    __shared__ __half tile[32][40];
    const int s  = blockIdx.z;
    const __half* src = qkv + (size_t)s * SEQ * QKVN + 2 * DIM;
    __half* dst = vt + (size_t)s * DIM * SEQ;
    const int k0 = blockIdx.x * 32, d0 = blockIdx.y * 32;
    const int tx = threadIdx.x & 31, ty = threadIdx.x >> 5;
    #pragma unroll
    for (int j = 0; j < 4; ++j)
        tile[ty + 8 * j][tx] = src[(size_t)(k0 + ty + 8 * j) * QKVN + d0 + tx];
    __syncthreads();
    #pragma unroll
    for (int j = 0; j < 4; ++j)
        dst[(size_t)(d0 + ty + 8 * j) * SEQ + k0 + tx] = tile[tx][ty + 8 * j];
}

// ---------------------------------------------------------------------------
// Row softmax over fp16 scores, in place: p = softmax(s / 16).
// ---------------------------------------------------------------------------
__global__ __launch_bounds__(256)
void softmax_h(__half* __restrict__ S, float scale)
{
    __half* row = S + (size_t)blockIdx.x * SEQ;
    const int tid = threadIdx.x;
    __shared__ float red[8];

    float v[16];
    #pragma unroll
    for (int j = 0; j < 2; ++j) {
        const __half2* p = (const __half2*)(row + (j * 256 + tid) * 8);
        #pragma unroll
        for (int q = 0; q < 4; ++q) {
            const float2 f = __half22float2(p[q]);
            v[j * 8 + 2 * q]     = f.x;
            v[j * 8 + 2 * q + 1] = f.y;
        }
    }

    float m = -1e30f;
    #pragma unroll
    for (int i = 0; i < 16; ++i) m = fmaxf(m, v[i]);
    #pragma unroll
    for (int o = 16; o; o >>= 1) m = fmaxf(m, __shfl_xor_sync(0xffffffffu, m, o));
    if ((tid & 31) == 0) red[tid >> 5] = m;
    __syncthreads();
    m = red[0];
    #pragma unroll
    for (int i = 1; i < 8; ++i) m = fmaxf(m, red[i]);
    __syncthreads();

    float sum = 0.f;
    #pragma unroll
    for (int i = 0; i < 16; ++i) {
        v[i] = __expf(scale * (v[i] - m));
        sum += v[i];
    }
    #pragma unroll
    for (int o = 16; o; o >>= 1) sum += __shfl_xor_sync(0xffffffffu, sum, o);
    if ((tid & 31) == 0) red[tid >> 5] = sum;
    __syncthreads();
    sum = 0.f;
    #pragma unroll
    for (int i = 0; i < 8; ++i) sum += red[i];
    const float inv = 1.f / sum;

    #pragma unroll
    for (int j = 0; j < 2; ++j) {
        __half2* p = (__half2*)(row + (j * 256 + tid) * 8);
        #pragma unroll
        for (int q = 0; q < 4; ++q)
            p[q] = __floats2half2_rn(v[j * 8 + 2 * q] * inv, v[j * 8 + 2 * q + 1] * inv);
    }
}

// ---------------------------------------------------------------------------
// Round-copy all three token views -> fp16 scratch (single launch)
// ---------------------------------------------------------------------------
__global__ __launch_bounds__(256)
void round_copy3(const float* __restrict__ t0, const float* __restrict__ t1,
                 const float* __restrict__ t2, __half* __restrict__ dst, int ntok)
{
    const int i = blockIdx.x * 1024 + threadIdx.x * 4;
    if (i >= 3 * ntok) return;
    const float* src;
    int off;
    if (i < ntok)            { src = t0; off = i; }
    else if (i < 2 * ntok)   { src = t1; off = i - ntok; }
    else                     { src = t2; off = i - 2 * ntok; }
    float4 v = *(const float4*)(src + off);
    *(__half2*)(dst + i)     = __floats2half2_rn(v.x, v.y);
    *(__half2*)(dst + i + 2) = __floats2half2_rn(v.z, v.w);
}

// ---------------------------------------------------------------------------
// Pack [wq;wk;wv] -> g_wqkv (fp16) and biases -> g_bqkv (fp32)
// ---------------------------------------------------------------------------
__global__ __launch_bounds__(256)
void build_wqkv(const float* __restrict__ wq, const float* __restrict__ wk,
                const float* __restrict__ wv, const float* __restrict__ bq,
                const float* __restrict__ bk, const float* __restrict__ bv,
                __half* __restrict__ W, float* __restrict__ Bb)
{
    const int idx = blockIdx.x * 256 + threadIdx.x;
    if (idx >= QKVN * DIM) return;
    const int r = idx / DIM, c = idx % DIM;
    const float* w = (r < DIM) ? wq : (r < 2 * DIM) ? wk : wv;
    W[idx] = __float2half_rn(w[(r & (DIM - 1)) * DIM + c]);
    if (idx < QKVN) {
        const float* b = (idx < DIM) ? bq : (idx < 2 * DIM) ? bk : bv;
        Bb[idx] = b[idx & (DIM - 1)];
    }
}

// ---------------------------------------------------------------------------
// y = LayerNorm(att + tokens) * g + b -> concatenated x buffer (fp32)
// ---------------------------------------------------------------------------
__global__ __launch_bounds__(256)
void resid_ln_kernel(const float* __restrict__ att, const float* __restrict__ tok,
                     const float* __restrict__ g, const float* __restrict__ b,
                     float* __restrict__ xout, int view)
{
    const long row = blockIdx.x;
    const int d = threadIdx.x;
    __shared__ float red[8];

    const float v = att[row * DIM + d] + tok[row * DIM + d];

    float s = v;
    #pragma unroll
    for (int o = 16; o; o >>= 1) s += __shfl_xor_sync(0xffffffffu, s, o);
    if ((d & 31) == 0) red[d >> 5] = s;
    __syncthreads();
    float mean = 0.f;
    #pragma unroll
    for (int i = 0; i < 8; ++i) mean += red[i];
    mean *= (1.f / DIM);
    __syncthreads();

    const float c = v - mean;
    float s2 = c * c;
    #pragma unroll
    for (int o = 16; o; o >>= 1) s2 += __shfl_xor_sync(0xffffffffu, s2, o);
    if ((d & 31) == 0) red[d >> 5] = s2;
    __syncthreads();
    float var = 0.f;
    #pragma unroll
    for (int i = 0; i < 8; ++i) var += red[i];
    var *= (1.f / DIM);

    const float y = c * rsqrtf(var + 1e-5f) * g[d] + b[d];
    xout[row * IN3 + (long)view * DIM + d] = y;
}

// ---------------------------------------------------------------------------
// Combined weight: [base_w | spline_w * scaler] -> fp16
// ---------------------------------------------------------------------------
__global__ __launch_bounds__(256)
void build_w_kernel(const float* __restrict__ bw, const float* __restrict__ sw,
                    const float* __restrict__ sc, __half* __restrict__ W)
{
    const long idx = (long)blockIdx.x * blockDim.x + threadIdx.x;
    if (idx >= (long)DIM * IN3) return;
    const int o = (int)(idx / IN3);
    const int i = (int)(idx % IN3);
    W[(long)o * KCOMB + i] = __float2half_rn(bw[(long)o * IN3 + i]);
    const float s = sc[(long)o * IN3 + i];
    const float* swp = sw + ((long)o * IN3 + i) * NB;
    __half* wp = W + (long)o * KCOMB + IN3 + (long)i * NB;
    #pragma unroll
    for (int f = 0; f < NB; ++f) wp[f] = __float2half_rn(swp[f] * s);
}

// ---------------------------------------------------------------------------
// Combined A: [silu(x) | cubic b-spline bases] -> fp16
// ---------------------------------------------------------------------------
__global__ __launch_bounds__(256)
void build_a_kernel(const float* __restrict__ x, __half* __restrict__ A)
{
    const long idx = (long)blockIdx.x * blockDim.x + threadIdx.x;
    if (idx >= (long)NROWS * IN3) return;
    const long n = idx / IN3;
    const int i = (int)(idx % IN3);
    const float v = x[idx];

    const float sig = 1.f / (1.f + __expf(-v));
    A[n * KCOMB + i] = __float2half_rn(v * sig);

    const float h = 0.4f;
    float b[11];
    #pragma unroll
    for (int j = 0; j < 11; ++j) {
        const float gj  = -1.f + (j - 3) * h;
        const float gj1 = -1.f + (j - 2) * h;
        b[j] = (v >= gj && v < gj1) ? 1.f : 0.f;
    }
    #pragma unroll
    for (int k = 1; k <= 3; ++k) {
        #pragma unroll
        for (int j = 0; j <= 10 - k; ++j) {
            const float gj   = -1.f + (j - 3) * h;
            const float gjk  = -1.f + (j - 3 + k) * h;
            const float gj1  = -1.f + (j - 2) * h;
            const float gjk1 = -1.f + (j - 2 + k) * h;
            b[j] = (v - gj) / (gjk - gj) * b[j] + (gjk1 - v) / (gjk1 - gj1) * b[j + 1];
        }
    }
    __half* ap = A + n * KCOMB + IN3 + (long)i * NB;
    #pragma unroll
    for (int f = 0; f < NB; ++f) ap[f] = __float2half_rn(b[f]);
}

// ---------------------------------------------------------------------------
// out = part0 + part1 (split-K reduction, fixed order -> deterministic)
// ---------------------------------------------------------------------------
__global__ __launch_bounds__(256)
void add2_kernel(const float* __restrict__ p0, const float* __restrict__ p1,
                 float* __restrict__ out, int n)
{
    const int i = blockIdx.x * 1024 + threadIdx.x * 4;
    if (i >= n) return;
    float4 a = *(const float4*)(p0 + i);
    float4 b = *(const float4*)(p1 + i);
    a.x += b.x; a.y += b.y; a.z += b.z; a.w += b.w;
    *(float4*)(out + i) = a;
}

// ---------------------------------------------------------------------------
// Host launcher
// ---------------------------------------------------------------------------
extern "C" void kernel_launch(void* const* d_in, const int* in_sizes, int n_in,
                              void* d_out, int out_size)
{
    (void)in_sizes; (void)n_in; (void)out_size;

    const float* tok[NVIEW] = {(const float*)d_in[0], (const float*)d_in[1], (const float*)d_in[2]};
    const float* wq = (const float*)d_in[3];
    const float* bq = (const float*)d_in[4];
    const float* wk = (const float*)d_in[5];
    const float* bk = (const float*)d_in[6];
    const float* wv = (const float*)d_in[7];
    const float* bv = (const float*)d_in[8];
    // d_in[9] = view_emb: per-query constant bias -> softmax-invariant -> unused
    const float* lng[NVIEW] = {(const float*)d_in[10], (const float*)d_in[12], (const float*)d_in[14]};
    const float* lnb[NVIEW] = {(const float*)d_in[11], (const float*)d_in[13], (const float*)d_in[15]};
    const float* bw = (const float*)d_in[16];
    const float* sw = (const float*)d_in[17];
    const float* sc = (const float*)d_in[18];

    __half *ptok, *pwqkv, *pqkv, *pvt, *ps, *pa, *pw;
    float *pbqkv, *att, *x, *ppart;
    cudaGetSymbolAddress((void**)&ptok,  g_tok);
    cudaGetSymbolAddress((void**)&pwqkv, g_wqkv);
    cudaGetSymbolAddress((void**)&pbqkv, g_bqkv);
    cudaGetSymbolAddress((void**)&pqkv,  g_qkv);
    cudaGetSymbolAddress((void**)&pvt,   g_vt);
    cudaGetSymbolAddress((void**)&ps,    g_s);
    cudaGetSymbolAddress((void**)&att,   g_att);
    cudaGetSymbolAddress((void**)&x,     g_x);
    cudaGetSymbolAddress((void**)&pa,    g_a);
    cudaGetSymbolAddress((void**)&pw,    g_w);
    cudaGetSymbolAddress((void**)&ppart, g_part);

    const int SMEM = STAGES * STG_H * 2 * (int)sizeof(__half);   // 110592 B
    cudaFuncSetAttribute(hgemm<true>,  cudaFuncAttributeMaxDynamicSharedMemorySize, SMEM);
    cudaFuncSetAttribute(hgemm<false>, cudaFuncAttributeMaxDynamicSharedMemorySize, SMEM);

    const long qkvSlice = (long)SEQ * QKVN;
    const long sStride  = (long)SEQ * SEQ;

    // 0) pack tokens (fp16, one launch) and qkv weights
    const int ntok = NROWS * DIM;
    round_copy3<<<(3 * ntok + 1023) / 1024, 256>>>(tok[0], tok[1], tok[2], ptok, ntok);
    build_wqkv<<<(QKVN * DIM + 255) / 256, 256>>>(wq, wk, wv, bq, bk, bv, pwqkv, pbqkv);

    // 1) fused QKV: [24576,768] = tok @ Wqkv^T + bqkv -> fp16
    {
        dim3 grid(QKVN / 128, ROWS3 / 128, 1);
        hgemm<true><<<grid, 256, SMEM>>>(ptok, DIM, pwqkv, DIM, pqkv, QKVN,
                                         DIM, 0, 0, 0, pbqkv);
    }

    // 1b) transpose V slices -> g_vt
    {
        dim3 grid(SEQ / 32, DIM / 32, NVB);
        transpose_v<<<grid, 256>>>(pqkv, pvt);
    }

    // 2) scores = Q @ K^T (fp16 out), all 6 slices
    {
        dim3 grid(SEQ / 128, SEQ / 128, NVB);
        hgemm<true><<<grid, 256, SMEM>>>(pqkv, QKVN, pqkv + DIM, QKVN, ps, SEQ,
                                         DIM, qkvSlice, qkvSlice, sStride, nullptr);
    }

    // 3) softmax(scores / 16) in place -> fp16 probs
    softmax_h<<<NVB * SEQ, 256>>>(ps, 0.0625f);

    // 4) att = P @ Vt^T (NT, fp32 out)
    {
        dim3 grid(DIM / 128, SEQ / 128, NVB);
        hgemm<false><<<grid, 256, SMEM>>>(ps, SEQ, pvt, SEQ, att, DIM,
                                          SEQ, sStride, (long)DIM * SEQ, (long)SEQ * DIM, nullptr);
    }

    // 5) LayerNorm(att + tokens) -> concat x (fp32)
    for (int vi = 0; vi < NVIEW; ++vi)
        resid_ln_kernel<<<NROWS, 256>>>(att + (long)vi * NROWS * DIM, tok[vi],
                                        lng[vi], lnb[vi], x, vi);

    // 6) combined weight / combined A (fp16)
    build_w_kernel<<<(DIM * IN3 + 255) / 256, 256>>>(bw, sw, sc, pw);
    build_a_kernel<<<(int)(((long)NROWS * IN3 + 255) / 256), 256>>>(x, pa);

    // 7) out = A @ W^T via split-K=2 (256 CTAs), then deterministic add
    {
        dim3 grid(DIM / 128, NROWS / 128, 2);
        hgemm<false><<<grid, 256, SMEM>>>(pa, KCOMB, pw, KCOMB, ppart, DIM,
                                          KCOMB / 2, KCOMB / 2, KCOMB / 2,
                                          (long)NROWS * DIM, nullptr);
        add2_kernel<<<(NROWS * DIM + 1023) / 1024, 256>>>(
            ppart, ppart + (long)NROWS * DIM, (float*)d_out, NROWS * DIM);
    }
}